// round 2
// baseline (speedup 1.0000x reference)
#include <cuda_runtime.h>
#include <cstdint>

// Problem constants (match reference)
#define NU    100000
#define NI    50000
#define NN    150000            // NU + NI
#define K     64
#define K2    32                // float2 per row
#define FEAT  1024
#define NE    3000000
#define BATCH 16384
#define NBLK_SCAN 147           // ceil(150000/1024)

// ---------------- scratch (static device allocations; no cudaMalloc) --------
__device__ int    g_deg[NN];
__device__ int    g_fill[NN];
__device__ float  g_dinv[NN];
__device__ int    g_rowptr[NN + 1];
__device__ int    g_bsum[256];
__device__ int    g_boff[256];
__device__ int    g_col[2 * NE];            // 24 MB
__device__ float2 g_acc[NN * K2];           // 38.4 MB
__device__ float2 g_yA[NN * K2];            // 38.4 MB
__device__ float2 g_yB[NN * K2];            // 38.4 MB
__device__ float  g_proj[BATCH * K];        // 4 MB

// ---------------- kernels ---------------------------------------------------

__global__ void k_zero_counters() {
    int i = blockIdx.x * blockDim.x + threadIdx.x;
    if (i < NN) { g_deg[i] = 0; g_fill[i] = 0; }
}

__global__ void k_count(const int* __restrict__ ue, const int* __restrict__ ie) {
    int e = blockIdx.x * blockDim.x + threadIdx.x;
    if (e >= NE) return;
    atomicAdd(&g_deg[ue[e]], 1);
    atomicAdd(&g_deg[NU + ie[e]], 1);
}

__global__ void k_dinv() {
    int i = blockIdx.x * blockDim.x + threadIdx.x;
    if (i >= NN) return;
    int d = g_deg[i];
    g_dinv[i] = (d > 0) ? rsqrtf((float)d) : 0.0f;
}

// Block-level exclusive scan of degrees (Hillis-Steele on 1024 elems)
__global__ void k_scanA() {
    __shared__ int sh[1024];
    int idx = blockIdx.x * 1024 + threadIdx.x;
    int v = (idx < NN) ? g_deg[idx] : 0;
    sh[threadIdx.x] = v;
    __syncthreads();
    for (int off = 1; off < 1024; off <<= 1) {
        int t = (threadIdx.x >= off) ? sh[threadIdx.x - off] : 0;
        __syncthreads();
        sh[threadIdx.x] += t;
        __syncthreads();
    }
    if (idx < NN) g_rowptr[idx] = sh[threadIdx.x] - v;  // exclusive
    if (threadIdx.x == 1023) g_bsum[blockIdx.x] = sh[1023];
}

__global__ void k_scanB() {
    if (threadIdx.x == 0) {
        int run = 0;
        for (int b = 0; b < NBLK_SCAN; b++) { int v = g_bsum[b]; g_boff[b] = run; run += v; }
        g_rowptr[NN] = run;
    }
}

__global__ void k_scanC() {
    int idx = blockIdx.x * blockDim.x + threadIdx.x;
    if (idx < NN) g_rowptr[idx] += g_boff[idx >> 10];
}

__global__ void k_fill(const int* __restrict__ ue, const int* __restrict__ ie) {
    int e = blockIdx.x * blockDim.x + threadIdx.x;
    if (e >= NE) return;
    int u = ue[e], it = NU + ie[e];
    int p = atomicAdd(&g_fill[u], 1);
    g_col[g_rowptr[u] + p] = it;
    int q = atomicAdd(&g_fill[it], 1);
    g_col[g_rowptr[it] + q] = u;
}

// acc = x0 ; yA = dinv * x0
__global__ void k_init(const float2* __restrict__ Gu, const float2* __restrict__ Gi) {
    int idx = blockIdx.x * blockDim.x + threadIdx.x;
    if (idx >= NN * K2) return;
    int n = idx >> 5;
    int c = idx & 31;
    float2 x0 = (n < NU) ? Gu[(size_t)n * K2 + c] : Gi[(size_t)(n - NU) * K2 + c];
    g_acc[idx] = x0;
    float dv = g_dinv[n];
    g_yA[idx] = make_float2(x0.x * dv, x0.y * dv);
}

// One warp per node: x_next[d] = dinv[d] * sum_{s in N(d)} y_in[s]
// acc += x_next ; y_out = dinv[d] * x_next
// flip==0: yin=g_yA, yout=g_yB.  flip==1: yin=g_yB, yout=g_yA.
// (Device symbols are resolved in DEVICE code — never passed from host.)
__global__ void k_prop(int flip) {
    const float2* __restrict__ yin = flip ? (const float2*)g_yB : (const float2*)g_yA;
    float2* __restrict__ yout      = flip ? g_yA : g_yB;
    int w = (blockIdx.x * blockDim.x + threadIdx.x) >> 5;
    int lane = threadIdx.x & 31;
    if (w >= NN) return;
    int beg = g_rowptr[w], end = g_rowptr[w + 1];
    float sx = 0.f, sy = 0.f;
    int j = beg;
    for (; j + 4 <= end; j += 4) {
        int c0 = g_col[j], c1 = g_col[j + 1], c2 = g_col[j + 2], c3 = g_col[j + 3];
        float2 a0 = yin[(size_t)c0 * K2 + lane];
        float2 a1 = yin[(size_t)c1 * K2 + lane];
        float2 a2 = yin[(size_t)c2 * K2 + lane];
        float2 a3 = yin[(size_t)c3 * K2 + lane];
        sx += (a0.x + a1.x) + (a2.x + a3.x);
        sy += (a0.y + a1.y) + (a2.y + a3.y);
    }
    for (; j < end; j++) {
        float2 a = yin[(size_t)g_col[j] * K2 + lane];
        sx += a.x; sy += a.y;
    }
    float dv = g_dinv[w];
    float xx = sx * dv, xy = sy * dv;
    size_t o = (size_t)w * K2 + lane;
    float2 ac = g_acc[o];
    ac.x += xx; ac.y += xy;
    g_acc[o] = ac;
    yout[o] = make_float2(xx * dv, xy * dv);
}

// proj[b][k] = sum_f F[items[b]][f] * W[k][f] + bias[k]
// 64x64 output tile per block, BK=64, 256 threads (16x16), 4x4 micro-tile.
__global__ void k_gemm(const float* __restrict__ F, const float* __restrict__ W,
                       const float* __restrict__ bias, const int* __restrict__ items) {
    __shared__ float As[64][65];
    __shared__ float Bs[64][65];
    __shared__ int   its[64];
    int bm0 = blockIdx.x * 64;
    int tid = threadIdx.x;
    int tx = tid & 15, ty = tid >> 4;
    if (tid < 64) its[tid] = items[bm0 + tid];
    __syncthreads();
    float acc[4][4] = {};
    for (int f0 = 0; f0 < FEAT; f0 += 64) {
        #pragma unroll
        for (int i = 0; i < 16; i++) {
            int idx = tid + i * 256;
            int r = idx >> 6, c = idx & 63;
            As[r][c] = F[(size_t)its[r] * FEAT + f0 + c];
            Bs[c][r] = W[(size_t)r * FEAT + f0 + c];  // Bs[f][k]
        }
        __syncthreads();
        #pragma unroll
        for (int ff = 0; ff < 64; ff++) {
            float a[4], b[4];
            #pragma unroll
            for (int m = 0; m < 4; m++) a[m] = As[ty * 4 + m][ff];
            #pragma unroll
            for (int n = 0; n < 4; n++) b[n] = Bs[ff][tx * 4 + n];
            #pragma unroll
            for (int m = 0; m < 4; m++)
                #pragma unroll
                for (int n = 0; n < 4; n++)
                    acc[m][n] = fmaf(a[m], b[n], acc[m][n]);
        }
        __syncthreads();
    }
    #pragma unroll
    for (int m = 0; m < 4; m++)
        #pragma unroll
        for (int n = 0; n < 4; n++)
            g_proj[(size_t)(bm0 + ty * 4 + m) * K + tx * 4 + n] = acc[m][n] + bias[tx * 4 + n];
}

// One warp per batch element: out = dot(acc_u, acc_i)/16 + dot(Tu_u, proj_b)/max(||proj_b||,1e-12)
__global__ void k_final(const int* __restrict__ users, const int* __restrict__ items,
                        const float2* __restrict__ Tu, float* __restrict__ out) {
    int b = (blockIdx.x * blockDim.x + threadIdx.x) >> 5;
    int lane = threadIdx.x & 31;
    if (b >= BATCH) return;
    int u = users[b], it = items[b];
    float2 gu = g_acc[(size_t)u * K2 + lane];
    float2 gi = g_acc[(size_t)(NU + it) * K2 + lane];
    float d1 = gu.x * gi.x + gu.y * gi.y;
    float2 tu = Tu[(size_t)u * K2 + lane];
    const float2* pr2 = (const float2*)g_proj;
    float2 pr = pr2[(size_t)b * K2 + lane];
    float d2 = tu.x * pr.x + tu.y * pr.y;
    float ss = pr.x * pr.x + pr.y * pr.y;
    #pragma unroll
    for (int off = 16; off; off >>= 1) {
        d1 += __shfl_xor_sync(0xFFFFFFFFu, d1, off);
        d2 += __shfl_xor_sync(0xFFFFFFFFu, d2, off);
        ss += __shfl_xor_sync(0xFFFFFFFFu, ss, off);
    }
    if (lane == 0) {
        float nrm = sqrtf(ss);
        float den = fmaxf(nrm, 1e-12f);
        out[b] = d1 * (1.0f / 16.0f) + d2 / den;
    }
}

// ---------------- launch -----------------------------------------------------

extern "C" void kernel_launch(void* const* d_in, const int* in_sizes, int n_in,
                              void* d_out, int out_size) {
    const float* Gu     = (const float*)d_in[0];
    const float* Gi     = (const float*)d_in[1];
    const float* Tu     = (const float*)d_in[2];
    const float* F      = (const float*)d_in[3];
    const float* proj_w = (const float*)d_in[4];
    const float* proj_b = (const float*)d_in[5];
    const int*   ue     = (const int*)d_in[6];
    const int*   ie     = (const int*)d_in[7];
    const int*   users  = (const int*)d_in[8];
    const int*   items  = (const int*)d_in[9];
    float* out = (float*)d_out;

    k_zero_counters<<<(NN + 255) / 256, 256>>>();
    k_count<<<(NE + 255) / 256, 256>>>(ue, ie);
    k_dinv<<<(NN + 255) / 256, 256>>>();
    k_scanA<<<NBLK_SCAN, 1024>>>();
    k_scanB<<<1, 32>>>();
    k_scanC<<<(NN + 255) / 256, 256>>>();
    k_fill<<<(NE + 255) / 256, 256>>>(ue, ie);
    k_init<<<(NN * K2 + 255) / 256, 256>>>((const float2*)Gu, (const float2*)Gi);

    // 3 LightGCN layers: one warp per node, 8 warps per block
    const int PROP_BLOCKS = NN / 8;  // 150000/8 = 18750
    k_prop<<<PROP_BLOCKS, 256>>>(0);  // yA -> yB
    k_prop<<<PROP_BLOCKS, 256>>>(1);  // yB -> yA
    k_prop<<<PROP_BLOCKS, 256>>>(0);  // yA -> yB

    k_gemm<<<BATCH / 64, 256>>>(F, proj_w, proj_b, items);
    k_final<<<(BATCH * 32 + 255) / 256, 256>>>(users, items, (const float2*)Tu, out);
}